// round 3
// baseline (speedup 1.0000x reference)
#include <cuda_runtime.h>
#include <cuda_bf16.h>

// NeuMIP v1 single-res, round 3:
//  - back to 1 point/thread, 256 thr/block, __launch_bounds__(256,2) to cap
//    regs at 128 -> 16 warps/SM (fix the R2 latency-bound regression)
//  - packed fp32 FFMA2 (fma.rn.f32x2), weights transposed in smem [K][32],
//    weight rows loaded as ulonglong2 (LDS.128)

#define RESOL 512
#define RMASK 511
#define HID 32
#define NSLOPE 0.01f

typedef unsigned long long ull;

__device__ __forceinline__ float leaky(float x) {
    return x >= 0.0f ? x : NSLOPE * x;
}

__device__ __forceinline__ ull fma2(ull a, ull b, ull c) {
    ull d;
    asm("fma.rn.f32x2 %0, %1, %2, %3;" : "=l"(d) : "l"(a), "l"(b), "l"(c));
    return d;
}

__device__ __forceinline__ ull pack2(float lo, float hi) {
    ull d;
    asm("mov.b64 %0, {%1, %2};" : "=l"(d) : "f"(lo), "f"(hi));
    return d;
}

__device__ __forceinline__ void unpack2(ull v, float& lo, float& hi) {
    asm("mov.b64 {%0, %1}, %2;" : "=f"(lo), "=f"(hi) : "l"(v));
}

// 8-channel bilinear with wrap. Texel = 8 contiguous floats = 2x float4.
__device__ __forceinline__ void bilin8(const float4* __restrict__ t,
                                       float u, float v, float* __restrict__ o) {
    float px = u * (float)RESOL - 0.5f;
    float py = v * (float)RESOL - 0.5f;
    float fpx = floorf(px), fpy = floorf(py);
    float fx = px - fpx, fy = py - fpy;
    int ix = (int)fpx, iy = (int)fpy;
    int x0 = ix & RMASK, x1 = (ix + 1) & RMASK;
    int y0 = iy & RMASK, y1 = (iy + 1) & RMASK;
    float w00 = (1.0f - fx) * (1.0f - fy);
    float w01 = fx * (1.0f - fy);
    float w10 = (1.0f - fx) * fy;
    float w11 = fx * fy;
    const float4* p00 = t + (size_t)(y0 * RESOL + x0) * 2;
    const float4* p01 = t + (size_t)(y0 * RESOL + x1) * 2;
    const float4* p10 = t + (size_t)(y1 * RESOL + x0) * 2;
    const float4* p11 = t + (size_t)(y1 * RESOL + x1) * 2;
    float4 a00 = __ldg(p00),     b00 = __ldg(p00 + 1);
    float4 a01 = __ldg(p01),     b01 = __ldg(p01 + 1);
    float4 a10 = __ldg(p10),     b10 = __ldg(p10 + 1);
    float4 a11 = __ldg(p11),     b11 = __ldg(p11 + 1);
    o[0] = w00 * a00.x + w01 * a01.x + w10 * a10.x + w11 * a11.x;
    o[1] = w00 * a00.y + w01 * a01.y + w10 * a10.y + w11 * a11.y;
    o[2] = w00 * a00.z + w01 * a01.z + w10 * a10.z + w11 * a11.z;
    o[3] = w00 * a00.w + w01 * a01.w + w10 * a10.w + w11 * a11.w;
    o[4] = w00 * b00.x + w01 * b01.x + w10 * b10.x + w11 * b11.x;
    o[5] = w00 * b00.y + w01 * b01.y + w10 * b10.y + w11 * b11.y;
    o[6] = w00 * b00.z + w01 * b01.z + w10 * b10.z + w11 * b11.z;
    o[7] = w00 * b00.w + w01 * b01.w + w10 * b10.w + w11 * b11.w;
}

// One hidden layer, 1 point: out[j] = leaky(b[j] + sum_i in[i]*W[j,i]).
// wT is transposed [K][32]: wT[i*32+j] = W[j,i]. A ulonglong2 load at
// (i, 4k) yields packed pairs (W[4k],W[4k+1]),(W[4k+2],W[4k+3]) at input i.
template <int K>
__device__ __forceinline__ void layer1(const float* __restrict__ wT,
                                       const float* __restrict__ b,
                                       const float* __restrict__ in,
                                       float* __restrict__ out) {
    ull acc[16];
    const ull* b2 = reinterpret_cast<const ull*>(b);
#pragma unroll
    for (int k = 0; k < 16; k++) acc[k] = b2[k];
#pragma unroll
    for (int i = 0; i < K; i++) {
        ull a = pack2(in[i], in[i]);
        const ulonglong2* w2 = reinterpret_cast<const ulonglong2*>(wT + i * HID);
#pragma unroll
        for (int k = 0; k < 8; k++) {
            ulonglong2 w = w2[k];
            acc[2 * k]     = fma2(a, w.x, acc[2 * k]);
            acc[2 * k + 1] = fma2(a, w.y, acc[2 * k + 1]);
        }
    }
#pragma unroll
    for (int k = 0; k < 16; k++) {
        float x, y;
        unpack2(acc[k], x, y);
        out[2 * k]     = leaky(x);
        out[2 * k + 1] = leaky(y);
    }
}

struct __align__(16) SWeights {
    float ow0T[10 * HID];  float ob0[HID];
    float ow1T[HID * HID]; float ob1[HID];
    float ow2T[HID * HID]; float ob2[HID];
    float ow3[HID];        float ob3[4];
    float rw0T[12 * HID];  float rb0[HID];
    float rw1T[HID * HID]; float rb1[HID];
    float rw2T[HID * HID]; float rb2[HID];
    float rw3[3 * HID];    float rb3[4];
};

__device__ __forceinline__ void scopy(float* dst, const float* src, int n,
                                      int tid, int nt) {
    for (int i = tid; i < n; i += nt) dst[i] = src[i];
}

// src: [32][K] row-major -> dst: [K][32]
__device__ __forceinline__ void tcopy(float* dst, const float* src, int K,
                                      int tid, int nt) {
    for (int idx = tid; idx < HID * K; idx += nt) {
        int j = idx / K, i = idx - j * K;
        dst[i * HID + j] = src[idx];
    }
}

__global__ void __launch_bounds__(256, 2)
neumip_kernel(const float* __restrict__ cam,
              const float* __restrict__ light,
              const float* __restrict__ uv,
              const float* __restrict__ offset_tex,
              const float* __restrict__ rgb_tex,
              const float* __restrict__ ow0, const float* __restrict__ ob0,
              const float* __restrict__ ow1, const float* __restrict__ ob1,
              const float* __restrict__ ow2, const float* __restrict__ ob2,
              const float* __restrict__ ow3, const float* __restrict__ ob3,
              const float* __restrict__ rw0, const float* __restrict__ rb0,
              const float* __restrict__ rw1, const float* __restrict__ rb1,
              const float* __restrict__ rw2, const float* __restrict__ rb2,
              const float* __restrict__ rw3, const float* __restrict__ rb3,
              float* __restrict__ out, int n) {
    __shared__ SWeights s;
    const int tid = threadIdx.x;
    const int nt = blockDim.x;
    tcopy(s.ow0T, ow0, 10, tid, nt);  scopy(s.ob0, ob0, HID, tid, nt);
    tcopy(s.ow1T, ow1, HID, tid, nt); scopy(s.ob1, ob1, HID, tid, nt);
    tcopy(s.ow2T, ow2, HID, tid, nt); scopy(s.ob2, ob2, HID, tid, nt);
    scopy(s.ow3, ow3, HID, tid, nt);  scopy(s.ob3, ob3, 1, tid, nt);
    tcopy(s.rw0T, rw0, 12, tid, nt);  scopy(s.rb0, rb0, HID, tid, nt);
    tcopy(s.rw1T, rw1, HID, tid, nt); scopy(s.rb1, rb1, HID, tid, nt);
    tcopy(s.rw2T, rw2, HID, tid, nt); scopy(s.rb2, rb2, HID, tid, nt);
    scopy(s.rw3, rw3, 3 * HID, tid, nt); scopy(s.rb3, rb3, 3, tid, nt);
    __syncthreads();

    const int p = blockIdx.x * blockDim.x + tid;
    if (p >= n) return;

    const float2 c2 = __ldg(reinterpret_cast<const float2*>(cam) + p);
    const float2 t2 = __ldg(reinterpret_cast<const float2*>(uv) + p);
    const float cx = c2.x, cy = c2.y;
    const float u0 = t2.x, v0 = t2.y;

    // ---- offset texture gather + depth MLP ----
    float in[12];
    bilin8(reinterpret_cast<const float4*>(offset_tex), u0, v0, in);
    in[8] = cx;
    in[9] = cy;

    float ha[HID], hb[HID];
    layer1<10>(s.ow0T, s.ob0, in, ha);
    layer1<HID>(s.ow1T, s.ob1, ha, hb);
    layer1<HID>(s.ow2T, s.ob2, hb, ha);

    float depth = s.ob3[0];
#pragma unroll
    for (int i = 0; i < HID; i++) depth = fmaf(ha[i], s.ow3[i], depth);

    // ---- parallax offset ----
    float z2 = 1.0f - (cx * cx + cy * cy);
    float z = sqrtf(fmaxf(z2, 1e-6f));
    float sc = depth / z;
    float u1 = u0 + cx * sc;
    float v1 = v0 + cy * sc;

    // ---- rgb texture gather + rgb MLP ----
    const float2 l2 = __ldg(reinterpret_cast<const float2*>(light) + p);
    in[0] = l2.x;
    in[1] = l2.y;
    in[2] = cx;
    in[3] = cy;
    bilin8(reinterpret_cast<const float4*>(rgb_tex), u1, v1, in + 4);

    layer1<12>(s.rw0T, s.rb0, in, ha);
    layer1<HID>(s.rw1T, s.rb1, ha, hb);
    layer1<HID>(s.rw2T, s.rb2, hb, ha);

#pragma unroll
    for (int c = 0; c < 3; c++) {
        float acc = s.rb3[c];
        const float* w = s.rw3 + c * HID;
#pragma unroll
        for (int i = 0; i < HID; i++) acc = fmaf(ha[i], w[i], acc);
        out[3 * p + c] = acc;
    }
}

extern "C" void kernel_launch(void* const* d_in, const int* in_sizes, int n_in,
                              void* d_out, int out_size) {
    const float* cam        = (const float*)d_in[0];
    const float* light      = (const float*)d_in[1];
    const float* uv         = (const float*)d_in[2];
    const float* offset_tex = (const float*)d_in[3];
    const float* rgb_tex    = (const float*)d_in[4];
    const float* ow0 = (const float*)d_in[5];
    const float* ob0 = (const float*)d_in[6];
    const float* ow1 = (const float*)d_in[7];
    const float* ob1 = (const float*)d_in[8];
    const float* ow2 = (const float*)d_in[9];
    const float* ob2 = (const float*)d_in[10];
    const float* ow3 = (const float*)d_in[11];
    const float* ob3 = (const float*)d_in[12];
    const float* rw0 = (const float*)d_in[13];
    const float* rb0 = (const float*)d_in[14];
    const float* rw1 = (const float*)d_in[15];
    const float* rb1 = (const float*)d_in[16];
    const float* rw2 = (const float*)d_in[17];
    const float* rb2 = (const float*)d_in[18];
    const float* rw3 = (const float*)d_in[19];
    const float* rb3 = (const float*)d_in[20];

    const int n = in_sizes[0] / 2;  // camera_dir is (B, 2)
    const int threads = 256;
    const int blocks = (n + threads - 1) / threads;
    neumip_kernel<<<blocks, threads>>>(cam, light, uv, offset_tex, rgb_tex,
                                       ow0, ob0, ow1, ob1, ow2, ob2, ow3, ob3,
                                       rw0, rb0, rw1, rb1, rw2, rb2, rw3, rb3,
                                       (float*)d_out, n);
}

// round 4
// speedup vs baseline: 1.5092x; 1.5092x over previous
#include <cuda_runtime.h>
#include <cuda_bf16.h>

// NeuMIP v1, round 4: neuron-split lane pairs, 4 points per pair,
// activations staged in shared memory (in-place), FFMA2 everywhere.
//  lane = 2*g + h : g = point-group (0..15), h = neuron half (0..1)
//  thread accumulates 16 neurons x 4 points fully in registers (32 ull),
//  weights read once per 64 points per warp (broadcast LDS.128).

#define RESOL 512
#define RMASK 511
#define HID 32
#define NSLOPE 0.01f
#define THREADS 256
#define PTS_PER_BLOCK 512
#define ACT_STRIDE 512

typedef unsigned long long ull;

__device__ __forceinline__ float leaky(float x) {
    // slope < 1  =>  leaky(x) == max(x, 0.01*x)
    return fmaxf(x, NSLOPE * x);
}

__device__ __forceinline__ ull fma2(ull a, ull b, ull c) {
    ull d;
    asm("fma.rn.f32x2 %0, %1, %2, %3;" : "=l"(d) : "l"(a), "l"(b), "l"(c));
    return d;
}

__device__ __forceinline__ ull pack2(float lo, float hi) {
    ull d;
    asm("mov.b64 %0, {%1, %2};" : "=l"(d) : "f"(lo), "f"(hi));
    return d;
}

__device__ __forceinline__ void unpack2(ull v, float& lo, float& hi) {
    asm("mov.b64 {%0, %1}, %2;" : "=f"(lo), "=f"(hi) : "l"(v));
}

// 8-channel bilinear with wrap. Texel = 8 contiguous floats = 2x float4.
__device__ __forceinline__ void bilin8(const float4* __restrict__ t,
                                       float u, float v, float* __restrict__ o) {
    float px = u * (float)RESOL - 0.5f;
    float py = v * (float)RESOL - 0.5f;
    float fpx = floorf(px), fpy = floorf(py);
    float fx = px - fpx, fy = py - fpy;
    int ix = (int)fpx, iy = (int)fpy;
    int x0 = ix & RMASK, x1 = (ix + 1) & RMASK;
    int y0 = iy & RMASK, y1 = (iy + 1) & RMASK;
    float w00 = (1.0f - fx) * (1.0f - fy);
    float w01 = fx * (1.0f - fy);
    float w10 = (1.0f - fx) * fy;
    float w11 = fx * fy;
    const float4* p00 = t + (size_t)(y0 * RESOL + x0) * 2;
    const float4* p01 = t + (size_t)(y0 * RESOL + x1) * 2;
    const float4* p10 = t + (size_t)(y1 * RESOL + x0) * 2;
    const float4* p11 = t + (size_t)(y1 * RESOL + x1) * 2;
    float4 a00 = __ldg(p00),     b00 = __ldg(p00 + 1);
    float4 a01 = __ldg(p01),     b01 = __ldg(p01 + 1);
    float4 a10 = __ldg(p10),     b10 = __ldg(p10 + 1);
    float4 a11 = __ldg(p11),     b11 = __ldg(p11 + 1);
    o[0] = w00 * a00.x + w01 * a01.x + w10 * a10.x + w11 * a11.x;
    o[1] = w00 * a00.y + w01 * a01.y + w10 * a10.y + w11 * a11.y;
    o[2] = w00 * a00.z + w01 * a01.z + w10 * a10.z + w11 * a11.z;
    o[3] = w00 * a00.w + w01 * a01.w + w10 * a10.w + w11 * a11.w;
    o[4] = w00 * b00.x + w01 * b01.x + w10 * b10.x + w11 * b11.x;
    o[5] = w00 * b00.y + w01 * b01.y + w10 * b10.y + w11 * b11.y;
    o[6] = w00 * b00.z + w01 * b01.z + w10 * b10.z + w11 * b11.z;
    o[7] = w00 * b00.w + w01 * b01.w + w10 * b10.w + w11 * b11.w;
}

struct __align__(16) SWeights {
    float ow0T[10 * HID];  float ob0[HID];
    float ow1T[HID * HID]; float ob1[HID];
    float ow2T[HID * HID]; float ob2[HID];
    float ow3[HID];        float ob3[4];
    float rw0T[12 * HID];  float rb0[HID];
    float rw1T[HID * HID]; float rb1[HID];
    float rw2T[HID * HID]; float rb2[HID];
    float rw3[3 * HID];    float rb3[4];
};

__device__ __forceinline__ void scopy(float* dst, const float* src, int n,
                                      int tid, int nt) {
    for (int i = tid; i < n; i += nt) dst[i] = src[i];
}

// src: [32][K] row-major -> dst: [K][32]
__device__ __forceinline__ void tcopy(float* dst, const float* src, int K,
                                      int tid, int nt) {
    for (int idx = tid; idx < HID * K; idx += nt) {
        int j = idx / K, i = idx - j * K;
        dst[i * HID + j] = src[idx];
    }
}

// One layer: 16 output neurons (h*16..h*16+15) for 4 points (p4..p4+3),
// K inputs read from act rows [0..K), outputs written in-place to rows
// [h*16, h*16+16). Pair-thread hazard handled by __syncwarp around stores.
template <int K>
__device__ __forceinline__ void layer_pair(const float* __restrict__ wT,
                                           const float* __restrict__ bias,
                                           float* __restrict__ act,
                                           int p4, int h) {
    ull acc[4][8];
    const ull* b2 = reinterpret_cast<const ull*>(bias + h * 16);
#pragma unroll
    for (int k = 0; k < 8; k++) {
        ull b = b2[k];
        acc[0][k] = b; acc[1][k] = b; acc[2][k] = b; acc[3][k] = b;
    }
#pragma unroll
    for (int i = 0; i < K; i++) {
        float4 a4 = *reinterpret_cast<const float4*>(act + i * ACT_STRIDE + p4);
        ull a0 = pack2(a4.x, a4.x);
        ull a1 = pack2(a4.y, a4.y);
        ull a2 = pack2(a4.z, a4.z);
        ull a3 = pack2(a4.w, a4.w);
        const ulonglong2* w2 =
            reinterpret_cast<const ulonglong2*>(wT + i * HID + h * 16);
#pragma unroll
        for (int q = 0; q < 4; q++) {
            ulonglong2 w = w2[q];
            acc[0][2 * q]     = fma2(a0, w.x, acc[0][2 * q]);
            acc[0][2 * q + 1] = fma2(a0, w.y, acc[0][2 * q + 1]);
            acc[1][2 * q]     = fma2(a1, w.x, acc[1][2 * q]);
            acc[1][2 * q + 1] = fma2(a1, w.y, acc[1][2 * q + 1]);
            acc[2][2 * q]     = fma2(a2, w.x, acc[2][2 * q]);
            acc[2][2 * q + 1] = fma2(a2, w.y, acc[2][2 * q + 1]);
            acc[3][2 * q]     = fma2(a3, w.x, acc[3][2 * q]);
            acc[3][2 * q + 1] = fma2(a3, w.y, acc[3][2 * q + 1]);
        }
    }
    __syncwarp();  // pair thread must finish reading act before we overwrite
#pragma unroll
    for (int k = 0; k < 8; k++) {
        float lo0, hi0, lo1, hi1, lo2, hi2, lo3, hi3;
        unpack2(acc[0][k], lo0, hi0);
        unpack2(acc[1][k], lo1, hi1);
        unpack2(acc[2][k], lo2, hi2);
        unpack2(acc[3][k], lo3, hi3);
        int c = h * 16 + 2 * k;
        float4 vlo = make_float4(leaky(lo0), leaky(lo1), leaky(lo2), leaky(lo3));
        float4 vhi = make_float4(leaky(hi0), leaky(hi1), leaky(hi2), leaky(hi3));
        *reinterpret_cast<float4*>(act + c * ACT_STRIDE + p4) = vlo;
        *reinterpret_cast<float4*>(act + (c + 1) * ACT_STRIDE + p4) = vhi;
    }
    __syncwarp();  // stores visible to pair before next layer reads
}

__global__ void __launch_bounds__(THREADS, 2)
neumip_kernel(const float* __restrict__ cam,
              const float* __restrict__ light,
              const float* __restrict__ uv,
              const float* __restrict__ offset_tex,
              const float* __restrict__ rgb_tex,
              const float* __restrict__ ow0, const float* __restrict__ ob0,
              const float* __restrict__ ow1, const float* __restrict__ ob1,
              const float* __restrict__ ow2, const float* __restrict__ ob2,
              const float* __restrict__ ow3, const float* __restrict__ ob3,
              const float* __restrict__ rw0, const float* __restrict__ rb0,
              const float* __restrict__ rw1, const float* __restrict__ rb1,
              const float* __restrict__ rw2, const float* __restrict__ rb2,
              const float* __restrict__ rw3, const float* __restrict__ rb3,
              float* __restrict__ out, int n) {
    extern __shared__ float dyn[];
    SWeights* sw = reinterpret_cast<SWeights*>(dyn);
    float* act = dyn + sizeof(SWeights) / 4;  // [32][ACT_STRIDE]

    const int tid = threadIdx.x;
    tcopy(sw->ow0T, ow0, 10, tid, THREADS);  scopy(sw->ob0, ob0, HID, tid, THREADS);
    tcopy(sw->ow1T, ow1, HID, tid, THREADS); scopy(sw->ob1, ob1, HID, tid, THREADS);
    tcopy(sw->ow2T, ow2, HID, tid, THREADS); scopy(sw->ob2, ob2, HID, tid, THREADS);
    scopy(sw->ow3, ow3, HID, tid, THREADS);  scopy(sw->ob3, ob3, 1, tid, THREADS);
    tcopy(sw->rw0T, rw0, 12, tid, THREADS);  scopy(sw->rb0, rb0, HID, tid, THREADS);
    tcopy(sw->rw1T, rw1, HID, tid, THREADS); scopy(sw->rb1, rb1, HID, tid, THREADS);
    tcopy(sw->rw2T, rw2, HID, tid, THREADS); scopy(sw->rb2, rb2, HID, tid, THREADS);
    scopy(sw->rw3, rw3, 3 * HID, tid, THREADS); scopy(sw->rb3, rb3, 3, tid, THREADS);
    __syncthreads();

    const int lane = tid & 31;
    const int warp = tid >> 5;
    const int g = lane >> 1;
    const int h = lane & 1;
    const int p4 = warp * 64 + g * 4;                 // local point base (4 pts)
    const int block_base = blockIdx.x * PTS_PER_BLOCK;
    if (block_base >= n) return;

    const float2* cam2 = reinterpret_cast<const float2*>(cam);
    const float2* uv2p = reinterpret_cast<const float2*>(uv);
    const float2* li2 = reinterpret_cast<const float2*>(light);

    // ---- gather phase: this thread fills rows 0..9 for 2 of the 4 points ----
#pragma unroll
    for (int j = 0; j < 2; j++) {
        int lp = p4 + 2 * h + j;
        int gp = block_base + lp;
        float2 c2 = __ldg(cam2 + gp);
        float2 t2 = __ldg(uv2p + gp);
        float lat[8];
        bilin8(reinterpret_cast<const float4*>(offset_tex), t2.x, t2.y, lat);
#pragma unroll
        for (int c = 0; c < 8; c++) act[c * ACT_STRIDE + lp] = lat[c];
        act[8 * ACT_STRIDE + lp] = c2.x;
        act[9 * ACT_STRIDE + lp] = c2.y;
    }
    __syncwarp();

    // ---- depth MLP ----
    layer_pair<10>(sw->ow0T, sw->ob0, act, p4, h);
    layer_pair<HID>(sw->ow1T, sw->ob1, act, p4, h);
    layer_pair<HID>(sw->ow2T, sw->ob2, act, p4, h);

    // depth head: partial dot over own 16 chans for 4 pts, combine with pair
    float4 ds = make_float4(0.f, 0.f, 0.f, 0.f);
#pragma unroll
    for (int c = 0; c < 16; c++) {
        int row = h * 16 + c;
        float w = sw->ow3[row];
        float4 v = *reinterpret_cast<const float4*>(act + row * ACT_STRIDE + p4);
        ds.x = fmaf(v.x, w, ds.x);
        ds.y = fmaf(v.y, w, ds.y);
        ds.z = fmaf(v.z, w, ds.z);
        ds.w = fmaf(v.w, w, ds.w);
    }
    ds.x += __shfl_xor_sync(0xffffffffu, ds.x, 1);
    ds.y += __shfl_xor_sync(0xffffffffu, ds.y, 1);
    ds.z += __shfl_xor_sync(0xffffffffu, ds.z, 1);
    ds.w += __shfl_xor_sync(0xffffffffu, ds.w, 1);
    float ob3v = sw->ob3[0];
    // depths for the 2 points this thread gathers (lp = p4+2h+j)
    float dep0 = (h ? ds.z : ds.x) + ob3v;
    float dep1 = (h ? ds.w : ds.y) + ob3v;
    __syncwarp();

    // ---- parallax + rgb gather: fill rows 0..11 for 2 points ----
#pragma unroll
    for (int j = 0; j < 2; j++) {
        int lp = p4 + 2 * h + j;
        int gp = block_base + lp;
        float dep = j ? dep1 : dep0;
        float2 c2 = __ldg(cam2 + gp);
        float2 t2 = __ldg(uv2p + gp);
        float2 l2 = __ldg(li2 + gp);
        float z = sqrtf(fmaxf(1.0f - (c2.x * c2.x + c2.y * c2.y), 1e-6f));
        float sc = dep / z;
        float u1 = t2.x + c2.x * sc;
        float v1 = t2.y + c2.y * sc;
        float lat[8];
        bilin8(reinterpret_cast<const float4*>(rgb_tex), u1, v1, lat);
        act[0 * ACT_STRIDE + lp] = l2.x;
        act[1 * ACT_STRIDE + lp] = l2.y;
        act[2 * ACT_STRIDE + lp] = c2.x;
        act[3 * ACT_STRIDE + lp] = c2.y;
#pragma unroll
        for (int c = 0; c < 8; c++) act[(4 + c) * ACT_STRIDE + lp] = lat[c];
    }
    __syncwarp();

    // ---- rgb MLP ----
    layer_pair<12>(sw->rw0T, sw->rb0, act, p4, h);
    layer_pair<HID>(sw->rw1T, sw->rb1, act, p4, h);
    layer_pair<HID>(sw->rw2T, sw->rb2, act, p4, h);

    // rgb head: 3 outputs, partial over own 16 chans, combine with pair
    float4 r0 = make_float4(0.f, 0.f, 0.f, 0.f);
    float4 r1 = r0, r2 = r0;
#pragma unroll
    for (int c = 0; c < 16; c++) {
        int row = h * 16 + c;
        float4 v = *reinterpret_cast<const float4*>(act + row * ACT_STRIDE + p4);
        float w0 = sw->rw3[0 * HID + row];
        float w1 = sw->rw3[1 * HID + row];
        float w2 = sw->rw3[2 * HID + row];
        r0.x = fmaf(v.x, w0, r0.x); r0.y = fmaf(v.y, w0, r0.y);
        r0.z = fmaf(v.z, w0, r0.z); r0.w = fmaf(v.w, w0, r0.w);
        r1.x = fmaf(v.x, w1, r1.x); r1.y = fmaf(v.y, w1, r1.y);
        r1.z = fmaf(v.z, w1, r1.z); r1.w = fmaf(v.w, w1, r1.w);
        r2.x = fmaf(v.x, w2, r2.x); r2.y = fmaf(v.y, w2, r2.y);
        r2.z = fmaf(v.z, w2, r2.z); r2.w = fmaf(v.w, w2, r2.w);
    }
    r0.x += __shfl_xor_sync(0xffffffffu, r0.x, 1);
    r0.y += __shfl_xor_sync(0xffffffffu, r0.y, 1);
    r0.z += __shfl_xor_sync(0xffffffffu, r0.z, 1);
    r0.w += __shfl_xor_sync(0xffffffffu, r0.w, 1);
    r1.x += __shfl_xor_sync(0xffffffffu, r1.x, 1);
    r1.y += __shfl_xor_sync(0xffffffffu, r1.y, 1);
    r1.z += __shfl_xor_sync(0xffffffffu, r1.z, 1);
    r1.w += __shfl_xor_sync(0xffffffffu, r1.w, 1);
    r2.x += __shfl_xor_sync(0xffffffffu, r2.x, 1);
    r2.y += __shfl_xor_sync(0xffffffffu, r2.y, 1);
    r2.z += __shfl_xor_sync(0xffffffffu, r2.z, 1);
    r2.w += __shfl_xor_sync(0xffffffffu, r2.w, 1);

    float b0 = sw->rb3[0], b1 = sw->rb3[1], b2 = sw->rb3[2];
    // this thread writes its 2 points (lp = p4+2h+j)
    {
        int gp = block_base + p4 + 2 * h;
        float o00 = (h ? r0.z : r0.x) + b0;
        float o01 = (h ? r1.z : r1.x) + b1;
        float o02 = (h ? r2.z : r2.x) + b2;
        float o10 = (h ? r0.w : r0.y) + b0;
        float o11 = (h ? r1.w : r1.y) + b1;
        float o12 = (h ? r2.w : r2.y) + b2;
        out[3 * gp + 0] = o00;
        out[3 * gp + 1] = o01;
        out[3 * gp + 2] = o02;
        out[3 * gp + 3] = o10;
        out[3 * gp + 4] = o11;
        out[3 * gp + 5] = o12;
    }
}

extern "C" void kernel_launch(void* const* d_in, const int* in_sizes, int n_in,
                              void* d_out, int out_size) {
    const float* cam        = (const float*)d_in[0];
    const float* light      = (const float*)d_in[1];
    const float* uv         = (const float*)d_in[2];
    const float* offset_tex = (const float*)d_in[3];
    const float* rgb_tex    = (const float*)d_in[4];
    const float* ow0 = (const float*)d_in[5];
    const float* ob0 = (const float*)d_in[6];
    const float* ow1 = (const float*)d_in[7];
    const float* ob1 = (const float*)d_in[8];
    const float* ow2 = (const float*)d_in[9];
    const float* ob2 = (const float*)d_in[10];
    const float* ow3 = (const float*)d_in[11];
    const float* ob3 = (const float*)d_in[12];
    const float* rw0 = (const float*)d_in[13];
    const float* rb0 = (const float*)d_in[14];
    const float* rw1 = (const float*)d_in[15];
    const float* rb1 = (const float*)d_in[16];
    const float* rw2 = (const float*)d_in[17];
    const float* rb2 = (const float*)d_in[18];
    const float* rw3 = (const float*)d_in[19];
    const float* rb3 = (const float*)d_in[20];

    const int n = in_sizes[0] / 2;  // camera_dir is (B, 2)
    const int smem = (int)sizeof(SWeights) + 32 * ACT_STRIDE * (int)sizeof(float);
    cudaFuncSetAttribute(neumip_kernel,
                         cudaFuncAttributeMaxDynamicSharedMemorySize, smem);
    const int blocks = (n + PTS_PER_BLOCK - 1) / PTS_PER_BLOCK;
    neumip_kernel<<<blocks, THREADS, smem>>>(cam, light, uv, offset_tex, rgb_tex,
                                             ow0, ob0, ow1, ob1, ow2, ob2, ow3, ob3,
                                             rw0, rb0, rw1, rb1, rw2, rb2, rw3, rb3,
                                             (float*)d_out, n);
}